// round 6
// baseline (speedup 1.0000x reference)
#include <cuda_runtime.h>
#include <math.h>

static constexpr int N_ROWS = 16384;
static constexpr int C_COLS = 1000;
static constexpr int C_VEC  = C_COLS / 4;   // 250 float4 per row
static constexpr int N_PART = 1024;

__device__ float  g_alpha[C_COLS];
__device__ double g_part[N_PART];
__device__ int    g_done = 0;

// ---------------------------------------------------------------------------
// Kernel 1: one block builds label histogram -> alpha[] table; zeros partials.
// ---------------------------------------------------------------------------
__global__ __launch_bounds__(1024)
void alpha_kernel(const int* __restrict__ label) {
    __shared__ int sh_counts[C_COLS];

    for (int i = threadIdx.x; i < C_COLS; i += 1024) sh_counts[i] = 0;
    if (threadIdx.x < N_PART) g_part[threadIdx.x] = 0.0;
    if (threadIdx.x == 0) g_done = 0;
    __syncthreads();

    const int4* lp = reinterpret_cast<const int4*>(label);
    for (int i = threadIdx.x; i < N_ROWS / 4; i += 1024) {
        int4 l4 = lp[i];
        if (l4.x >= 0 && l4.x < C_COLS) atomicAdd(&sh_counts[l4.x], 1);
        if (l4.y >= 0 && l4.y < C_COLS) atomicAdd(&sh_counts[l4.y], 1);
        if (l4.z >= 0 && l4.z < C_COLS) atomicAdd(&sh_counts[l4.z], 1);
        if (l4.w >= 0 && l4.w < C_COLS) atomicAdd(&sh_counts[l4.w], 1);
    }
    __syncthreads();

    for (int c = threadIdx.x; c < C_COLS; c += 1024) {
        float ni = (float)sh_counts[c];
        float r  = ni * (1.0f / (float)N_ROWS);
        g_alpha[c] = (ni > 0.0f) ? (__expf(r - 1.0f) / r) : 0.0f;
    }
}

// ---------------------------------------------------------------------------
// Kernel 2: one BLOCK per row, one float4 per thread (n_LDG=1 per warp ->
// no L1tex queue overflow). Label logit extracted from registers via smem.
// ---------------------------------------------------------------------------
__global__ __launch_bounds__(256)
void row_kernel(const float* __restrict__ feature,
                const int* __restrict__ label,
                float* __restrict__ out) {
    const int row  = blockIdx.x;
    const int tid  = threadIdx.x;
    const int lane = tid & 31;
    const int wid  = tid >> 5;

    __shared__ float  sh_warp[8];
    __shared__ float  sh_xl;
    __shared__ int    sh_l;
    __shared__ int    sh_last;
    __shared__ double sh_dwarp[8];

    if (tid == 0) {
        int l = label[row];
        if (l < 0) l = 0;
        if (l >= C_COLS) l = C_COLS - 1;
        sh_l = l;
    }

    const bool active = tid < C_VEC;
    float4 v = make_float4(0.f, 0.f, 0.f, 0.f);
    if (active)
        v = reinterpret_cast<const float4*>(feature + (size_t)row * C_COLS)[tid];

    float s = 0.0f;
    if (active)
        s = __expf(v.x) + __expf(v.y) + __expf(v.z) + __expf(v.w);

    __syncthreads();                       // sh_l visible
    const int l = sh_l;
    if (tid == (l >> 2)) {
        int c = l & 3;
        sh_xl = (c == 0) ? v.x : (c == 1) ? v.y : (c == 2) ? v.z : v.w;
    }

    #pragma unroll
    for (int o = 16; o > 0; o >>= 1)
        s += __shfl_xor_sync(0xFFFFFFFFu, s, o);
    if (lane == 0) sh_warp[wid] = s;
    __syncthreads();                       // sh_warp + sh_xl visible

    if (tid == 0) {
        float tot = 0.0f;
        #pragma unroll
        for (int w = 0; w < 8; w++) tot += sh_warp[w];
        float al   = g_alpha[l];
        float logp = sh_xl - __logf(tot);
        float p    = __expf(logp);
        float omp  = 1.0f - p;
        atomicAdd(&g_part[row & (N_PART - 1)], (double)(al * omp * omp * logp));
        __threadfence();
        int prev = atomicAdd(&g_done, 1);
        sh_last = (prev == (int)gridDim.x - 1) ? 1 : 0;
        if (sh_last) __threadfence();      // order ticket-read before partial reads
    }
    __syncthreads();

    if (sh_last) {
        // Parallel reduction of the 1024 partials (last block only).
        double acc = 0.0;
        #pragma unroll
        for (int k = 0; k < N_PART / 256; k++)
            acc += __ldcg(&g_part[tid + k * 256]);   // L2 reads (bypass L1)
        #pragma unroll
        for (int o = 16; o > 0; o >>= 1)
            acc += __shfl_xor_sync(0xFFFFFFFFu, acc, o);
        if (lane == 0) sh_dwarp[wid] = acc;
        __syncthreads();
        if (tid == 0) {
            double tot = 0.0;
            #pragma unroll
            for (int w = 0; w < 8; w++) tot += sh_dwarp[w];
            out[0] = (float)(-tot / (double)N_ROWS);
            g_done = 0;                    // replay-safe reset
        }
    }
}

extern "C" void kernel_launch(void* const* d_in, const int* in_sizes, int n_in,
                              void* d_out, int out_size) {
    const float* feature = (const float*)d_in[0];
    const int*   label   = (const int*)d_in[1];
    float*       out     = (float*)d_out;

    alpha_kernel<<<1, 1024>>>(label);
    row_kernel<<<N_ROWS, 256>>>(feature, label, out);
}

// round 8
// speedup vs baseline: 2.5910x; 2.5910x over previous
#include <cuda_runtime.h>
#include <cstdint>
#include <math.h>

static constexpr int N_ROWS = 16384;
static constexpr int C_COLS = 1000;
static constexpr int ROWS_PER_BLOCK = 8;
static constexpr int THREADS = 256;
static constexpr int GRID = N_ROWS / ROWS_PER_BLOCK;   // 2048
static constexpr int N_PART = 1024;

__device__ float  g_alpha[C_COLS];
__device__ double g_part[N_PART];
__device__ int    g_done = 0;

__device__ __forceinline__ void cp_async16(unsigned int smem_addr, const void* gptr) {
    asm volatile("cp.async.cg.shared.global [%0], [%1], 16;"
                 :: "r"(smem_addr), "l"(gptr) : "memory");
}
__device__ __forceinline__ void cp_commit() {
    asm volatile("cp.async.commit_group;" ::: "memory");
}
template <int N>
__device__ __forceinline__ void cp_wait() {
    asm volatile("cp.async.wait_group %0;" :: "n"(N) : "memory");
}

// ---------------------------------------------------------------------------
// Kernel 1: one block builds label histogram -> alpha[] table; zeros partials.
// ---------------------------------------------------------------------------
__global__ __launch_bounds__(1024)
void alpha_kernel(const int* __restrict__ label) {
    __shared__ int sh_counts[C_COLS];

    for (int i = threadIdx.x; i < C_COLS; i += 1024) sh_counts[i] = 0;
    if (threadIdx.x < N_PART) g_part[threadIdx.x] = 0.0;
    if (threadIdx.x == 0) g_done = 0;
    __syncthreads();

    const int4* lp = reinterpret_cast<const int4*>(label);
    for (int i = threadIdx.x; i < N_ROWS / 4; i += 1024) {
        int4 l4 = lp[i];
        if (l4.x >= 0 && l4.x < C_COLS) atomicAdd(&sh_counts[l4.x], 1);
        if (l4.y >= 0 && l4.y < C_COLS) atomicAdd(&sh_counts[l4.y], 1);
        if (l4.z >= 0 && l4.z < C_COLS) atomicAdd(&sh_counts[l4.z], 1);
        if (l4.w >= 0 && l4.w < C_COLS) atomicAdd(&sh_counts[l4.w], 1);
    }
    __syncthreads();

    for (int c = threadIdx.x; c < C_COLS; c += 1024) {
        float ni = (float)sh_counts[c];
        float r  = ni * (1.0f / (float)N_ROWS);
        g_alpha[c] = (ni > 0.0f) ? (__expf(r - 1.0f) / r) : 0.0f;
    }
}

// ---------------------------------------------------------------------------
// Kernel 2: 8 rows per block via cp.async double-buffered smem staging.
// ---------------------------------------------------------------------------
__global__ __launch_bounds__(THREADS)
void row_kernel(const float* __restrict__ feature,
                const int* __restrict__ label,
                float* __restrict__ out) {
    const int tid  = threadIdx.x;
    const int lane = tid & 31;
    const int wid  = tid >> 5;
    const int row0 = blockIdx.x * ROWS_PER_BLOCK;

    __shared__ __align__(16) float sh_row[ROWS_PER_BLOCK * C_COLS]; // 32 KB
    __shared__ float  sh_ws[THREADS / 32][ROWS_PER_BLOCK];
    __shared__ int    sh_lab[ROWS_PER_BLOCK];
    __shared__ int    sh_last;
    __shared__ double sh_dwarp[THREADS / 32];

    if (tid < ROWS_PER_BLOCK) {
        int l = label[row0 + tid];
        if (l < 0) l = 0;
        if (l >= C_COLS) l = C_COLS - 1;
        sh_lab[tid] = l;
    }

    const bool active = tid < C_COLS / 4;   // 250 float4 per row
    const unsigned int smem_base = (unsigned int)__cvta_generic_to_shared(sh_row);
    const float* gbase = feature + (size_t)row0 * C_COLS + tid * 4;

    // Stage A: rows 0-3
    if (active) {
        #pragma unroll
        for (int r = 0; r < 4; r++)
            cp_async16(smem_base + (r * C_COLS + tid * 4) * 4, gbase + r * C_COLS);
    }
    cp_commit();
    // Stage B: rows 4-7
    if (active) {
        #pragma unroll
        for (int r = 4; r < 8; r++)
            cp_async16(smem_base + (r * C_COLS + tid * 4) * 4, gbase + r * C_COLS);
    }
    cp_commit();

    float s[ROWS_PER_BLOCK];
    #pragma unroll
    for (int r = 0; r < ROWS_PER_BLOCK; r++) s[r] = 0.0f;

    cp_wait<1>();          // stage A complete
    __syncthreads();
    if (active) {
        #pragma unroll
        for (int r = 0; r < 4; r++) {
            float4 v = *reinterpret_cast<const float4*>(&sh_row[r * C_COLS + tid * 4]);
            s[r] = __expf(v.x) + __expf(v.y) + __expf(v.z) + __expf(v.w);
        }
    }

    cp_wait<0>();          // stage B complete
    __syncthreads();
    if (active) {
        #pragma unroll
        for (int r = 4; r < 8; r++) {
            float4 v = *reinterpret_cast<const float4*>(&sh_row[r * C_COLS + tid * 4]);
            s[r] = __expf(v.x) + __expf(v.y) + __expf(v.z) + __expf(v.w);
        }
    }

    // Warp-reduce each row sum, stash per-warp results.
    #pragma unroll
    for (int r = 0; r < ROWS_PER_BLOCK; r++) {
        float x = s[r];
        #pragma unroll
        for (int o = 16; o > 0; o >>= 1)
            x += __shfl_xor_sync(0xFFFFFFFFu, x, o);
        if (lane == 0) sh_ws[wid][r] = x;
    }
    __syncthreads();

    // Threads 0-7: finish row tid, one spread double atomic each.
    if (tid < ROWS_PER_BLOCK) {
        float S = 0.0f;
        #pragma unroll
        for (int w = 0; w < THREADS / 32; w++) S += sh_ws[w][tid];
        int   l    = sh_lab[tid];
        float xl   = sh_row[tid * C_COLS + l];
        float logp = xl - __logf(S);
        float p    = __expf(logp);
        float omp  = 1.0f - p;
        atomicAdd(&g_part[(row0 + tid) & (N_PART - 1)],
                  (double)(g_alpha[l] * omp * omp * logp));
    }
    __syncthreads();

    if (tid == 0) {
        __threadfence();
        int prev = atomicAdd(&g_done, 1);
        sh_last = (prev == (int)gridDim.x - 1) ? 1 : 0;
        if (sh_last) __threadfence();
    }
    __syncthreads();

    if (sh_last) {
        double acc = 0.0;
        #pragma unroll
        for (int k = 0; k < N_PART / THREADS; k++)
            acc += __ldcg(&g_part[tid + k * THREADS]);
        #pragma unroll
        for (int o = 16; o > 0; o >>= 1)
            acc += __shfl_xor_sync(0xFFFFFFFFu, acc, o);
        if (lane == 0) sh_dwarp[wid] = acc;
        __syncthreads();
        if (tid == 0) {
            double tot = 0.0;
            #pragma unroll
            for (int w = 0; w < THREADS / 32; w++) tot += sh_dwarp[w];
            out[0] = (float)(-tot / (double)N_ROWS);
            g_done = 0;    // replay-safe reset
        }
    }
}

extern "C" void kernel_launch(void* const* d_in, const int* in_sizes, int n_in,
                              void* d_out, int out_size) {
    const float* feature = (const float*)d_in[0];
    const int*   label   = (const int*)d_in[1];
    float*       out     = (float*)d_out;

    alpha_kernel<<<1, 1024>>>(label);
    row_kernel<<<GRID, THREADS>>>(feature, label, out);
}

// round 9
// speedup vs baseline: 2.9506x; 1.1388x over previous
#include <cuda_runtime.h>
#include <cstdint>
#include <math.h>

static constexpr int N_ROWS = 16384;
static constexpr int C_COLS = 1000;
static constexpr int C_VEC  = C_COLS / 4;      // 250 float4 per row
static constexpr int THREADS = 256;
static constexpr int GRID_ROW = 444;           // 3 CTAs/SM * 148 SMs
static constexpr int GW = GRID_ROW * (THREADS / 32);  // 3552 warps total
static constexpr int N_PART = 1024;

__device__ float  g_alpha[C_COLS];
__device__ double g_part[N_PART];
__device__ int    g_done = 0;

// ---------------------------------------------------------------------------
// Kernel 1: one block builds label histogram -> alpha[] table; zeros partials.
// (Measured ~free in wall time next to the row kernel.)
// ---------------------------------------------------------------------------
__global__ __launch_bounds__(1024)
void alpha_kernel(const int* __restrict__ label) {
    __shared__ int sh_counts[C_COLS];

    for (int i = threadIdx.x; i < C_COLS; i += 1024) sh_counts[i] = 0;
    if (threadIdx.x < N_PART) g_part[threadIdx.x] = 0.0;
    if (threadIdx.x == 0) g_done = 0;
    __syncthreads();

    const int4* lp = reinterpret_cast<const int4*>(label);
    for (int i = threadIdx.x; i < N_ROWS / 4; i += 1024) {
        int4 l4 = lp[i];
        if (l4.x >= 0 && l4.x < C_COLS) atomicAdd(&sh_counts[l4.x], 1);
        if (l4.y >= 0 && l4.y < C_COLS) atomicAdd(&sh_counts[l4.y], 1);
        if (l4.z >= 0 && l4.z < C_COLS) atomicAdd(&sh_counts[l4.z], 1);
        if (l4.w >= 0 && l4.w < C_COLS) atomicAdd(&sh_counts[l4.w], 1);
    }
    __syncthreads();

    for (int c = threadIdx.x; c < C_COLS; c += 1024) {
        float ni = (float)sh_counts[c];
        float r  = ni * (1.0f / (float)N_ROWS);
        g_alpha[c] = (ni > 0.0f) ? (__expf(r - 1.0f) / r) : 0.0f;
    }
}

// ---------------------------------------------------------------------------
// Row kernel: persistent warps, each owning ceil(16384/3552)=5 rows,
// double-buffered loads so the LSU is continuously fed (large T_CTA ->
// L1tex-queue contention spread collapses toward the 1.1 floor).
// ---------------------------------------------------------------------------
__device__ __forceinline__ void load_row(float4* buf, const float4* rp, int lane) {
    #pragma unroll
    for (int k = 0; k < 8; k++) {
        int idx = lane + k * 32;
        if (idx < C_VEC) buf[k] = rp[idx];
        else             buf[k] = make_float4(0.f, 0.f, 0.f, 0.f);
    }
}

__device__ __forceinline__ float sumexp_row(const float4* buf, int lane) {
    float s = 0.0f;
    #pragma unroll
    for (int k = 0; k < 8; k++) {
        int idx = lane + k * 32;
        if (idx < C_VEC) {
            s += __expf(buf[k].x) + __expf(buf[k].y)
               + __expf(buf[k].z) + __expf(buf[k].w);
        }
    }
    #pragma unroll
    for (int o = 16; o > 0; o >>= 1)
        s += __shfl_xor_sync(0xFFFFFFFFu, s, o);
    return s;  // full row sum, uniform across warp
}

__global__ __launch_bounds__(THREADS, 3)
void row_kernel(const float* __restrict__ feature,
                const int* __restrict__ label,
                float* __restrict__ out) {
    const int tid  = threadIdx.x;
    const int lane = tid & 31;
    const int wid  = tid >> 5;
    const int gw   = blockIdx.x * (THREADS / 32) + wid;   // 0..GW-1

    __shared__ int    sh_last;
    __shared__ double sh_dwarp[THREADS / 32];

    // ---- Prefetch this warp's per-row epilogue data (lanes 0..4) ----------
    // Row for iteration 'it' is gw + it*GW; lane 'it' owns it.
    const int myrow = gw + lane * GW;
    float xl = 0.0f, al = 0.0f;
    if (lane < 5 && myrow < N_ROWS) {
        int l = label[myrow];
        if (l < 0) l = 0;
        if (l >= C_COLS) l = C_COLS - 1;
        xl = __ldg(&feature[(size_t)myrow * C_COLS + l]);
        al = g_alpha[l];
    }

    // ---- Main double-buffered loop ----------------------------------------
    float4 bufA[8], bufB[8];
    const float4* fp = reinterpret_cast<const float4*>(feature);

    int rowA = gw;
    if (rowA < N_ROWS)
        load_row(bufA, fp + (size_t)rowA * C_VEC, lane);

    int it = 0;
    while (rowA < N_ROWS) {
        int rowB = rowA + GW;
        if (rowB < N_ROWS)
            load_row(bufB, fp + (size_t)rowB * C_VEC, lane);

        // compute A
        {
            float S = sumexp_row(bufA, lane);
            if (lane == it) {
                float logp = xl - __logf(S);
                float p    = __expf(logp);
                float omp  = 1.0f - p;
                atomicAdd(&g_part[rowA & (N_PART - 1)],
                          (double)(al * omp * omp * logp));
            }
        }

        int rowA2 = rowA + 2 * GW;
        if (rowA2 < N_ROWS)
            load_row(bufA, fp + (size_t)rowA2 * C_VEC, lane);

        // compute B
        if (rowB < N_ROWS) {
            float S = sumexp_row(bufB, lane);
            if (lane == it + 1) {
                float logp = xl - __logf(S);
                float p    = __expf(logp);
                float omp  = 1.0f - p;
                atomicAdd(&g_part[rowB & (N_PART - 1)],
                          (double)(al * omp * omp * logp));
            }
        }

        rowA = rowA2;
        it += 2;
    }

    // ---- Ticket + last-block final reduction ------------------------------
    __syncthreads();
    if (tid == 0) {
        __threadfence();
        int prev = atomicAdd(&g_done, 1);
        sh_last = (prev == (int)gridDim.x - 1) ? 1 : 0;
        if (sh_last) __threadfence();
    }
    __syncthreads();

    if (sh_last) {
        double acc = 0.0;
        #pragma unroll
        for (int k = 0; k < N_PART / THREADS; k++)
            acc += __ldcg(&g_part[tid + k * THREADS]);
        #pragma unroll
        for (int o = 16; o > 0; o >>= 1)
            acc += __shfl_xor_sync(0xFFFFFFFFu, acc, o);
        if (lane == 0) sh_dwarp[wid] = acc;
        __syncthreads();
        if (tid == 0) {
            double tot = 0.0;
            #pragma unroll
            for (int w = 0; w < THREADS / 32; w++) tot += sh_dwarp[w];
            out[0] = (float)(-tot / (double)N_ROWS);
            g_done = 0;    // replay-safe reset
        }
    }
}

extern "C" void kernel_launch(void* const* d_in, const int* in_sizes, int n_in,
                              void* d_out, int out_size) {
    const float* feature = (const float*)d_in[0];
    const int*   label   = (const int*)d_in[1];
    float*       out     = (float*)d_out;

    alpha_kernel<<<1, 1024>>>(label);
    row_kernel<<<GRID_ROW, THREADS>>>(feature, label, out);
}